// round 9
// baseline (speedup 1.0000x reference)
#include <cuda_runtime.h>
#include <cuda_bf16.h>
#include <math.h>
#include <stdint.h>

// Problem constants
#define B_ 2
#define N_ 12288
#define D_ 256
#define NW (N_ / 32)          // bitmask words per row = 384
#define CONF_THRESH 0.8f
#define JSPLIT 3
// bf16 1-pass sim abs error bound ~0.004; candidate filter threshold:
#define CAND_T 0.784f

// ---------------- device scratch (no allocations allowed) ----------------
__device__ __nv_bfloat16 g_Vhi[(size_t)B_ * N_ * D_];
__device__ __nv_bfloat16 g_Rhi[(size_t)B_ * N_ * D_];
__device__ float    g_Vf[(size_t)B_ * N_ * D_];
__device__ float    g_Rf[(size_t)B_ * N_ * D_];
__device__ unsigned g_bm[(size_t)B_ * N_ * NW];   // per-row candidate bitmask
__device__ int      g_nval[B_];
__device__ int      g_ninv[B_];
__device__ int      g_nconf[B_];
__device__ double   g_contrib[B_];
__device__ int      g_mask_mode;         // 0=int32, 1=uint8, 2=float32

// SMEM layout (bytes):
//   A tile : [0, 65536)        = 128 rows x 256 k bf16 (32 u16B/row), SW128 atoms
//   B bufs : [65536, 196608)   = 2 buffers x (256 cols x 128 k bf16)
#define SM_A    0u
#define SM_B    65536u
#define SMEM_BYTES 196608

// ---------------- small helpers ----------------
__device__ __forceinline__ uint32_t smem_u32_addr(const void* p) {
    uint32_t a;
    asm("{ .reg .u64 t; cvta.to.shared.u64 t, %1; cvt.u32.u64 %0, t; }"
        : "=r"(a) : "l"(p));
    return a;
}
__device__ __forceinline__ uint32_t sw128(uint32_t off) {
    return off ^ ((off >> 3) & 0x70u);
}
__device__ __forceinline__ void ldmatrix_x4(uint32_t* r, uint32_t addr) {
    asm volatile("ldmatrix.sync.aligned.m8n8.x4.shared.b16 {%0,%1,%2,%3}, [%4];"
                 : "=r"(r[0]), "=r"(r[1]), "=r"(r[2]), "=r"(r[3]) : "r"(addr));
}
__device__ __forceinline__ void mma16816(float* c, const uint32_t* a,
                                         uint32_t b0, uint32_t b1) {
    asm volatile(
        "mma.sync.aligned.m16n8k16.row.col.f32.bf16.bf16.f32 "
        "{%0,%1,%2,%3}, {%4,%5,%6,%7}, {%8,%9}, {%0,%1,%2,%3};"
        : "+f"(c[0]), "+f"(c[1]), "+f"(c[2]), "+f"(c[3])
        : "r"(a[0]), "r"(a[1]), "r"(a[2]), "r"(a[3]), "r"(b0), "r"(b1));
}
__device__ __forceinline__ void cp_async16(uint32_t saddr, const void* gaddr, int sz) {
    asm volatile("cp.async.ca.shared.global [%0], [%1], 16, %2;"
                 :: "r"(saddr), "l"(gaddr), "r"(sz));
}
__device__ __forceinline__ void cp_commit() {
    asm volatile("cp.async.commit_group;");
}
template <int N>
__device__ __forceinline__ void cp_wait() {
    asm volatile("cp.async.wait_group %0;" :: "n"(N));
}
// fire-and-forget OR into global (RED.OR, no return)
__device__ __forceinline__ void red_or(unsigned* addr, unsigned val) {
    asm volatile("red.global.or.b32 [%0], %1;" :: "l"(addr), "r"(val) : "memory");
}

// ---------------- init ----------------
__global__ void init_kernel() {
    int i = blockIdx.x * blockDim.x + threadIdx.x;
    if (i < B_) {
        g_nval[i] = 0; g_ninv[i] = 0; g_nconf[i] = 0; g_contrib[i] = 0.0;
    }
}

__global__ void zero_bm_kernel() {
    size_t i = (size_t)blockIdx.x * blockDim.x + threadIdx.x;
    size_t total = (size_t)B_ * N_ * NW / 4;
    uint4 z = make_uint4(0u, 0u, 0u, 0u);
    for (; i < total; i += (size_t)gridDim.x * blockDim.x)
        ((uint4*)g_bm)[i] = z;
}

// ---------------- mask dtype detection ----------------
__global__ void detect_kernel(const unsigned char* __restrict__ mraw) {
    __shared__ int s_f3f, s_foff;
    if (threadIdx.x == 0) { s_f3f = 0; s_foff = 0; }
    __syncthreads();
    int f3f = 0, foff = 0;
    for (int i = threadIdx.x; i < B_ * N_; i += blockDim.x) {
        unsigned char c = mraw[i];
        if ((i & 3) == 3 && c == 0x3f) f3f = 1;
        if ((i & 3) != 0 && c != 0)    foff = 1;
    }
    if (f3f)  atomicOr(&s_f3f, 1);
    if (foff) atomicOr(&s_foff, 1);
    __syncthreads();
    if (threadIdx.x == 0) g_mask_mode = s_f3f ? 2 : (s_foff ? 1 : 0);
}

// ---------------- normalize + compact (one warp per point) ----------------
__global__ void norm_compact_kernel(const float* __restrict__ feat,
                                    const void*  __restrict__ mraw) {
    int gw   = (int)((blockIdx.x * blockDim.x + threadIdx.x) >> 5);
    int lane = threadIdx.x & 31;
    if (gw >= B_ * N_) return;
    int b = gw / N_;

    int mv = 0;
    if (lane == 0) {
        int mode = g_mask_mode;
        if (mode == 0)      mv = (((const int*)mraw)[gw] != 0);
        else if (mode == 1) mv = (((const unsigned char*)mraw)[gw] != 0);
        else                mv = (((const float*)mraw)[gw] != 0.0f);
    }
    mv = __shfl_sync(0xffffffffu, mv, 0);

    const float* src = feat + (size_t)gw * D_;
    float4 v0 = ((const float4*)src)[lane];
    float4 v1 = ((const float4*)src)[lane + 32];
    float ss = v0.x * v0.x + v0.y * v0.y + v0.z * v0.z + v0.w * v0.w
             + v1.x * v1.x + v1.y * v1.y + v1.z * v1.z + v1.w * v1.w;
#pragma unroll
    for (int o = 16; o; o >>= 1) ss += __shfl_xor_sync(0xffffffffu, ss, o);
    float inv = 1.0f / fmaxf(sqrtf(ss), 1e-12f);
    v0.x *= inv; v0.y *= inv; v0.z *= inv; v0.w *= inv;
    v1.x *= inv; v1.y *= inv; v1.z *= inv; v1.w *= inv;

    int slot = 0;
    if (lane == 0)
        slot = atomicAdd(mv ? &g_nval[b] : &g_ninv[b], 1);
    slot = __shfl_sync(0xffffffffu, slot, 0);

    size_t base = ((size_t)b * N_ + slot) * D_;
    __nv_bfloat16* dh = (mv ? g_Vhi : g_Rhi) + base;
    float*         df = (mv ? g_Vf  : g_Rf)  + base;

    __nv_bfloat162 h0 = __floats2bfloat162_rn(v0.x, v0.y);
    __nv_bfloat162 h1 = __floats2bfloat162_rn(v0.z, v0.w);
    uint2 h; h.x = *(uint32_t*)&h0; h.y = *(uint32_t*)&h1;
    ((uint2*)dh)[lane] = h;
    h0 = __floats2bfloat162_rn(v1.x, v1.y);
    h1 = __floats2bfloat162_rn(v1.z, v1.w);
    h.x = *(uint32_t*)&h0; h.y = *(uint32_t*)&h1;
    ((uint2*)dh)[32 + lane] = h;
    ((float4*)df)[lane]      = v0;
    ((float4*)df)[lane + 32] = v1;
}

// ---------------- pass 1: approx bf16 HMMA, set candidate bits ------------
// grid (N_/128, B_, JSPLIT), 256 threads (8 warps: 2 m-warps x 4 n-warps,
// warp tile 64x64). CTA tile 128 rows x 256 cols. A resident, B streamed in
// (256 cols x 128 k) chunks double-buffered. Epilogue: RED.OR candidate bits
// (approx sim > CAND_T) into per-row bitmask. No sims materialized.
__global__ __launch_bounds__(256, 1) void maxsim_p1() {
    extern __shared__ __align__(1024) char smem[];
    int b = blockIdx.y;
    int ni = g_ninv[b], nv = g_nval[b];
    int row0 = blockIdx.x * 128;
    if (row0 >= ni || nv <= 0) return;

    int tiles_total = (nv + 255) >> 8;
    int tiles_per   = (tiles_total + JSPLIT - 1) / JSPLIT;
    int jbeg = blockIdx.z * tiles_per * 256;
    int jend = min(nv, jbeg + tiles_per * 256);
    if (jbeg >= jend) return;

    uint32_t sb = smem_u32_addr(smem);
    int tid = threadIdx.x;
    int lane = tid & 31, warp = tid >> 5;
    int warp_m = warp & 1, warp_n = warp >> 1;   // 2 x 4 warp grid

    const __nv_bfloat16* Rhi_b = g_Rhi + (size_t)b * N_ * D_;
    const __nv_bfloat16* Vhi_b = g_Vhi + (size_t)b * N_ * D_;
    unsigned* bm_b = g_bm + (size_t)b * N_ * NW;

    // ---- resident A tile: 128 rows x 32 u16B-units (512B/row), SW128 atoms
#pragma unroll
    for (int it = 0; it < 16; ++it) {
        int u = tid + it * 256;            // 0..4095
        int row = u >> 5;
        int ku  = u & 31;
        int gr  = min(row0 + row, ni - 1);
        const uint4* src = (const uint4*)(Rhi_b + (size_t)gr * D_) + ku;
        uint32_t off = SM_A
                     + (uint32_t)((row >> 3) * 4 + (ku >> 3)) * 1024u
                     + (uint32_t)(row & 7) * 128u + (uint32_t)(ku & 7) * 16u;
        *(uint4*)(smem + sw128(off)) = *src;
    }

    float acc[4][8][4];
#pragma unroll
    for (int mf = 0; mf < 4; ++mf)
#pragma unroll
        for (int nf = 0; nf < 8; ++nf)
#pragma unroll
            for (int q = 0; q < 4; ++q) acc[mf][nf][q] = 0.0f;

    int Tj = (jend - jbeg + 255) >> 8;
    int NC = Tj * 2;                       // 2 k128 chunks per j-tile

    auto cp_chunk = [&](int c, int bufsel) {
        int jt = c >> 1, kc = c & 1;
        int col0 = jbeg + jt * 256;
#pragma unroll
        for (int i = 0; i < 16; ++i) {
            int u = tid + i * 256;          // 0..4095
            int col = u >> 4;
            int ku  = u & 15;
            int gc  = col0 + col;
            const void* src = (const void*)(Vhi_b + (size_t)gc * D_ + kc * 128 + ku * 8);
            uint32_t off = SM_B + (uint32_t)bufsel * 65536u
                         + (uint32_t)((col >> 3) * 2 + (ku >> 3)) * 1024u
                         + (uint32_t)(col & 7) * 128u + (uint32_t)(ku & 7) * 16u;
            cp_async16(sb + sw128(off), src, (gc < jend) ? 16 : 0);
        }
        cp_commit();
    };

    cp_chunk(0, 0);
    __syncthreads();   // A tile visible

    for (int i = 0; i < NC; ++i) {
        int bufsel = i & 1;
        int kc = i & 1;
        if (i + 1 < NC) { cp_chunk(i + 1, (i + 1) & 1); cp_wait<1>(); }
        else            { cp_wait<0>(); }
        __syncthreads();

#pragma unroll
        for (int kk = 0; kk < 8; ++kk) {
            uint32_t a[4][4];
#pragma unroll
            for (int mf = 0; mf < 4; ++mf) {
                int row = warp_m * 64 + mf * 16 + (lane & 15);
                int ku  = (kc * 8 + kk) * 2 + (lane >> 4);
                uint32_t off = SM_A
                             + (uint32_t)((row >> 3) * 4 + (ku >> 3)) * 1024u
                             + (uint32_t)(row & 7) * 128u
                             + (uint32_t)(ku & 7) * 16u;
                ldmatrix_x4(a[mf], sb + sw128(off));
            }
            uint32_t bf[4][4];
#pragma unroll
            for (int nf2 = 0; nf2 < 4; ++nf2) {
                int col = warp_n * 64 + nf2 * 16 + (lane & 15);
                int ku  = kk * 2 + (lane >> 4);
                uint32_t off = SM_B + (uint32_t)bufsel * 65536u
                             + (uint32_t)((col >> 3) * 2 + (ku >> 3)) * 1024u
                             + (uint32_t)(col & 7) * 128u
                             + (uint32_t)(ku & 7) * 16u;
                ldmatrix_x4(bf[nf2], sb + sw128(off));
            }
#pragma unroll
            for (int mf = 0; mf < 4; ++mf)
#pragma unroll
                for (int nf2 = 0; nf2 < 4; ++nf2) {
                    mma16816(acc[mf][nf2 * 2],     a[mf], bf[nf2][0], bf[nf2][2]);
                    mma16816(acc[mf][nf2 * 2 + 1], a[mf], bf[nf2][1], bf[nf2][3]);
                }
        }

        if (kc == 1) {
            // end of j-tile: RED.OR candidate bits, reset accumulators.
            int jt = i >> 1;
            int colb = jbeg + jt * 256 + warp_n * 64 + 2 * (lane & 3);
#pragma unroll
            for (int mf = 0; mf < 4; ++mf) {
                int r0 = row0 + warp_m * 64 + mf * 16 + (lane >> 2);
#pragma unroll
                for (int nf = 0; nf < 8; ++nf) {
                    float* c = acc[mf][nf];
                    int cc = colb + nf * 8;
#pragma unroll
                    for (int q = 0; q < 4; ++q) {
                        if (c[q] > CAND_T) {
                            int rr = r0 + ((q >> 1) ? 8 : 0);
                            int col = cc + (q & 1);
                            if (rr < ni)
                                red_or(bm_b + (size_t)rr * NW + (col >> 5),
                                       1u << (col & 31));
                        }
                        c[q] = 0.0f;
                    }
                }
            }
        }
        __syncthreads();
    }
}

// ---------------- rescore: exact fp32 max over candidate bits ------------
// One warp per invalid row. Each lane owns 6 bitmask words, extracts set
// bits, computes exact fp32 dots lane-locally; one warp max-reduce at end.
__global__ void rescore_kernel() {
    int gw   = (int)((blockIdx.x * blockDim.x + threadIdx.x) >> 5);
    int lane = threadIdx.x & 31;
    if (gw >= B_ * N_) return;
    int b = gw / N_, row = gw - b * N_;
    int ni = g_ninv[b], nv = g_nval[b];
    if (row >= ni || nv <= 0) return;

    const unsigned* bmr = g_bm + ((size_t)b * N_ + row) * NW;
    const float* rf = g_Rf + ((size_t)b * N_ + row) * D_;
    const float* vb = g_Vf + (size_t)b * N_ * D_;

    float best = -INFINITY;
#pragma unroll
    for (int w6 = 0; w6 < NW / 32; ++w6) {
        int widx = w6 * 32 + lane;
        unsigned w = bmr[widx];
        while (w) {
            int bit = __ffs(w) - 1;
            w &= w - 1;
            int col = widx * 32 + bit;
            const float4* vc = (const float4*)(vb + (size_t)col * D_);
            const float4* rr = (const float4*)rf;
            float s = 0.0f;
#pragma unroll
            for (int t = 0; t < 64; ++t) {
                float4 x = vc[t], y = rr[t];
                s = fmaf(x.x, y.x, s); s = fmaf(x.y, y.y, s);
                s = fmaf(x.z, y.z, s); s = fmaf(x.w, y.w, s);
            }
            best = fmaxf(best, s);
        }
    }
#pragma unroll
    for (int o = 16; o; o >>= 1)
        best = fmaxf(best, __shfl_xor_sync(0xffffffffu, best, o));
    if (lane == 0 && best > CONF_THRESH) {
        atomicAdd(&g_contrib[b], (double)(1.0f - best));
        atomicAdd(&g_nconf[b], 1);
    }
}

// ---------------- finalize ----------------
__global__ void finalize_kernel(float* out) {
    if (threadIdx.x == 0 && blockIdx.x == 0) {
        double tl = 0.0, tp = 0.0;
        for (int b = 0; b < B_; ++b) {
            int ni = g_ninv[b], nvv = g_nval[b], nc = g_nconf[b];
            bool active = (nc > 0) && (nvv > 0) && (ni > 0);
            if (active) {
                double pseudo = g_contrib[b] / (double)(nc > 1 ? nc : 1);
                tl += pseudo * (double)ni;
                tp += (double)ni;
            }
        }
        out[0] = (tp > 0.0) ? (float)(0.01 * tl / tp) : 0.0f;
    }
}

// ---------------- launch ----------------
extern "C" void kernel_launch(void* const* d_in, const int* in_sizes, int n_in,
                              void* d_out, int out_size) {
    int fi = 0, mi = 1;
    if (n_in >= 2 && in_sizes[0] < in_sizes[1]) { fi = 1; mi = 0; }
    const float* feat = (const float*)d_in[fi];
    const void*  mask = d_in[mi];

    cudaFuncSetAttribute(maxsim_p1, cudaFuncAttributeMaxDynamicSharedMemorySize,
                         SMEM_BYTES);

    init_kernel<<<1, 32>>>();
    zero_bm_kernel<<<592, 256>>>();
    detect_kernel<<<1, 1024>>>((const unsigned char*)mask);
    norm_compact_kernel<<<(B_ * N_ * 32 + 255) / 256, 256>>>(feat, mask);
    dim3 g(N_ / 128, B_, JSPLIT);
    maxsim_p1<<<g, 256, SMEM_BYTES>>>();
    rescore_kernel<<<(B_ * N_ * 32 + 255) / 256, 256>>>();
    finalize_kernel<<<1, 32>>>((float*)d_out);
}

// round 10
// speedup vs baseline: 2.2889x; 2.2889x over previous
#include <cuda_runtime.h>
#include <cuda_bf16.h>
#include <cuda_fp16.h>
#include <math.h>
#include <stdint.h>

// Problem constants
#define B_ 2
#define N_ 12288
#define D_ 256
#define CONF_THRESH 0.8f
#define JSPLIT 3
// error bounds: bf16 mma sim err <= 0.0039, +fp16 store rounding <= 0.0044
#define GATE_SKIP 0.005f
#define GATE_CAND 0.010f

// ---------------- device scratch (no allocations allowed) ----------------
__device__ __nv_bfloat16 g_Vhi[(size_t)B_ * N_ * D_];
__device__ __nv_bfloat16 g_Rhi[(size_t)B_ * N_ * D_];
__device__ float    g_Vf[(size_t)B_ * N_ * D_];
__device__ float    g_Rf[(size_t)B_ * N_ * D_];
__device__ __half   g_sims[(size_t)B_ * N_ * N_];   // approx sims, fp16
__device__ int      g_nval[B_];
__device__ int      g_ninv[B_];
__device__ int      g_nconf[B_];
__device__ unsigned g_rmax[B_ * N_];     // monotonic-encoded approx row max
__device__ double   g_contrib[B_];
__device__ int      g_mask_mode;         // 0=int32, 1=uint8, 2=float32

// SMEM layout (bytes):
//   A tile : [0, 65536)        = 128 rows x 256 k bf16 (32 u16B/row), SW128 atoms
//   B bufs : [65536, 196608)   = 2 buffers x (256 cols x 128 k bf16)
//   rowmax : [196608, 198656)  = 4 x 128 floats
#define SM_A    0u
#define SM_B    65536u
#define SM_MAX  196608u
#define SMEM_BYTES 198656

// ---------------- small helpers ----------------
__device__ __forceinline__ uint32_t smem_u32_addr(const void* p) {
    uint32_t a;
    asm("{ .reg .u64 t; cvta.to.shared.u64 t, %1; cvt.u32.u64 %0, t; }"
        : "=r"(a) : "l"(p));
    return a;
}
__device__ __forceinline__ uint32_t sw128(uint32_t off) {
    return off ^ ((off >> 3) & 0x70u);
}
__device__ __forceinline__ void ldmatrix_x4(uint32_t* r, uint32_t addr) {
    asm volatile("ldmatrix.sync.aligned.m8n8.x4.shared.b16 {%0,%1,%2,%3}, [%4];"
                 : "=r"(r[0]), "=r"(r[1]), "=r"(r[2]), "=r"(r[3]) : "r"(addr));
}
__device__ __forceinline__ void mma16816(float* c, const uint32_t* a,
                                         uint32_t b0, uint32_t b1) {
    asm volatile(
        "mma.sync.aligned.m16n8k16.row.col.f32.bf16.bf16.f32 "
        "{%0,%1,%2,%3}, {%4,%5,%6,%7}, {%8,%9}, {%0,%1,%2,%3};"
        : "+f"(c[0]), "+f"(c[1]), "+f"(c[2]), "+f"(c[3])
        : "r"(a[0]), "r"(a[1]), "r"(a[2]), "r"(a[3]), "r"(b0), "r"(b1));
}
__device__ __forceinline__ void cp_async16(uint32_t saddr, const void* gaddr, int sz) {
    asm volatile("cp.async.ca.shared.global [%0], [%1], 16, %2;"
                 :: "r"(saddr), "l"(gaddr), "r"(sz));
}
__device__ __forceinline__ void cp_commit() {
    asm volatile("cp.async.commit_group;");
}
template <int N>
__device__ __forceinline__ void cp_wait() {
    asm volatile("cp.async.wait_group %0;" :: "n"(N));
}
__device__ __forceinline__ unsigned enc_max(float m) {
    int rep = __float_as_int(m);
    return (rep < 0) ? ~((unsigned)rep) : ((unsigned)rep | 0x80000000u);
}
__device__ __forceinline__ float dec_max(unsigned key) {
    return (key & 0x80000000u) ? __uint_as_float(key & 0x7fffffffu)
                               : __uint_as_float(~key);
}

// ---------------- init ----------------
__global__ void init_kernel() {
    int i = blockIdx.x * blockDim.x + threadIdx.x;
    if (i < B_ * N_) g_rmax[i] = 0u;
    if (i < B_) {
        g_nval[i] = 0; g_ninv[i] = 0; g_nconf[i] = 0; g_contrib[i] = 0.0;
    }
}

// ---------------- mask dtype detection ----------------
__global__ void detect_kernel(const unsigned char* __restrict__ mraw) {
    __shared__ int s_f3f, s_foff;
    if (threadIdx.x == 0) { s_f3f = 0; s_foff = 0; }
    __syncthreads();
    int f3f = 0, foff = 0;
    for (int i = threadIdx.x; i < B_ * N_; i += blockDim.x) {
        unsigned char c = mraw[i];
        if ((i & 3) == 3 && c == 0x3f) f3f = 1;
        if ((i & 3) != 0 && c != 0)    foff = 1;
    }
    if (f3f)  atomicOr(&s_f3f, 1);
    if (foff) atomicOr(&s_foff, 1);
    __syncthreads();
    if (threadIdx.x == 0) g_mask_mode = s_f3f ? 2 : (s_foff ? 1 : 0);
}

// ---------------- normalize + compact (one warp per point) ----------------
__global__ void norm_compact_kernel(const float* __restrict__ feat,
                                    const void*  __restrict__ mraw) {
    int gw   = (int)((blockIdx.x * blockDim.x + threadIdx.x) >> 5);
    int lane = threadIdx.x & 31;
    if (gw >= B_ * N_) return;
    int b = gw / N_;

    int mv = 0;
    if (lane == 0) {
        int mode = g_mask_mode;
        if (mode == 0)      mv = (((const int*)mraw)[gw] != 0);
        else if (mode == 1) mv = (((const unsigned char*)mraw)[gw] != 0);
        else                mv = (((const float*)mraw)[gw] != 0.0f);
    }
    mv = __shfl_sync(0xffffffffu, mv, 0);

    const float* src = feat + (size_t)gw * D_;
    float4 v0 = ((const float4*)src)[lane];
    float4 v1 = ((const float4*)src)[lane + 32];
    float ss = v0.x * v0.x + v0.y * v0.y + v0.z * v0.z + v0.w * v0.w
             + v1.x * v1.x + v1.y * v1.y + v1.z * v1.z + v1.w * v1.w;
#pragma unroll
    for (int o = 16; o; o >>= 1) ss += __shfl_xor_sync(0xffffffffu, ss, o);
    float inv = 1.0f / fmaxf(sqrtf(ss), 1e-12f);
    v0.x *= inv; v0.y *= inv; v0.z *= inv; v0.w *= inv;
    v1.x *= inv; v1.y *= inv; v1.z *= inv; v1.w *= inv;

    int slot = 0;
    if (lane == 0)
        slot = atomicAdd(mv ? &g_nval[b] : &g_ninv[b], 1);
    slot = __shfl_sync(0xffffffffu, slot, 0);

    size_t base = ((size_t)b * N_ + slot) * D_;
    __nv_bfloat16* dh = (mv ? g_Vhi : g_Rhi) + base;
    float*         df = (mv ? g_Vf  : g_Rf)  + base;

    __nv_bfloat162 h0 = __floats2bfloat162_rn(v0.x, v0.y);
    __nv_bfloat162 h1 = __floats2bfloat162_rn(v0.z, v0.w);
    uint2 h; h.x = *(uint32_t*)&h0; h.y = *(uint32_t*)&h1;
    ((uint2*)dh)[lane] = h;
    h0 = __floats2bfloat162_rn(v1.x, v1.y);
    h1 = __floats2bfloat162_rn(v1.z, v1.w);
    h.x = *(uint32_t*)&h0; h.y = *(uint32_t*)&h1;
    ((uint2*)dh)[32 + lane] = h;
    ((float4*)df)[lane]      = v0;
    ((float4*)df)[lane + 32] = v1;
}

// ---------------- pass 1: approx bf16 HMMA sims + row max (R7, proven) ----
__global__ __launch_bounds__(256, 1) void maxsim_p1() {
    extern __shared__ __align__(1024) char smem[];
    int b = blockIdx.y;
    int ni = g_ninv[b], nv = g_nval[b];
    int row0 = blockIdx.x * 128;
    if (row0 >= ni || nv <= 0) return;

    int tiles_total = (nv + 255) >> 8;
    int tiles_per   = (tiles_total + JSPLIT - 1) / JSPLIT;
    int jbeg = blockIdx.z * tiles_per * 256;
    int jend = min(nv, jbeg + tiles_per * 256);
    if (jbeg >= jend) return;

    uint32_t sb = smem_u32_addr(smem);
    int tid = threadIdx.x;
    int lane = tid & 31, warp = tid >> 5;
    int warp_m = warp & 1, warp_n = warp >> 1;   // 2 x 4 warp grid

    const __nv_bfloat16* Rhi_b = g_Rhi + (size_t)b * N_ * D_;
    const __nv_bfloat16* Vhi_b = g_Vhi + (size_t)b * N_ * D_;
    __half* sims_b = g_sims + (size_t)b * N_ * N_;

#pragma unroll
    for (int it = 0; it < 16; ++it) {
        int u = tid + it * 256;
        int row = u >> 5;
        int ku  = u & 31;
        int gr  = min(row0 + row, ni - 1);
        const uint4* src = (const uint4*)(Rhi_b + (size_t)gr * D_) + ku;
        uint32_t off = SM_A
                     + (uint32_t)((row >> 3) * 4 + (ku >> 3)) * 1024u
                     + (uint32_t)(row & 7) * 128u + (uint32_t)(ku & 7) * 16u;
        *(uint4*)(smem + sw128(off)) = *src;
    }

    float acc[4][8][4];
#pragma unroll
    for (int mf = 0; mf < 4; ++mf)
#pragma unroll
        for (int nf = 0; nf < 8; ++nf)
#pragma unroll
            for (int q = 0; q < 4; ++q) acc[mf][nf][q] = 0.0f;
    float rm[8];
#pragma unroll
    for (int r = 0; r < 8; ++r) rm[r] = -INFINITY;

    int Tj = (jend - jbeg + 255) >> 8;
    int NC = Tj * 2;

    auto cp_chunk = [&](int c, int bufsel) {
        int jt = c >> 1, kc = c & 1;
        int col0 = jbeg + jt * 256;
#pragma unroll
        for (int i = 0; i < 16; ++i) {
            int u = tid + i * 256;
            int col = u >> 4;
            int ku  = u & 15;
            int gc  = col0 + col;
            const void* src = (const void*)(Vhi_b + (size_t)gc * D_ + kc * 128 + ku * 8);
            uint32_t off = SM_B + (uint32_t)bufsel * 65536u
                         + (uint32_t)((col >> 3) * 2 + (ku >> 3)) * 1024u
                         + (uint32_t)(col & 7) * 128u + (uint32_t)(ku & 7) * 16u;
            cp_async16(sb + sw128(off), src, (gc < jend) ? 16 : 0);
        }
        cp_commit();
    };

    cp_chunk(0, 0);
    __syncthreads();

    for (int i = 0; i < NC; ++i) {
        int bufsel = i & 1;
        int kc = i & 1;
        if (i + 1 < NC) { cp_chunk(i + 1, (i + 1) & 1); cp_wait<1>(); }
        else            { cp_wait<0>(); }
        __syncthreads();

#pragma unroll
        for (int kk = 0; kk < 8; ++kk) {
            uint32_t a[4][4];
#pragma unroll
            for (int mf = 0; mf < 4; ++mf) {
                int row = warp_m * 64 + mf * 16 + (lane & 15);
                int ku  = (kc * 8 + kk) * 2 + (lane >> 4);
                uint32_t off = SM_A
                             + (uint32_t)((row >> 3) * 4 + (ku >> 3)) * 1024u
                             + (uint32_t)(row & 7) * 128u
                             + (uint32_t)(ku & 7) * 16u;
                ldmatrix_x4(a[mf], sb + sw128(off));
            }
            uint32_t bf[4][4];
#pragma unroll
            for (int nf2 = 0; nf2 < 4; ++nf2) {
                int col = warp_n * 64 + nf2 * 16 + (lane & 15);
                int ku  = kk * 2 + (lane >> 4);
                uint32_t off = SM_B + (uint32_t)bufsel * 65536u
                             + (uint32_t)((col >> 3) * 2 + (ku >> 3)) * 1024u
                             + (uint32_t)(col & 7) * 128u
                             + (uint32_t)(ku & 7) * 16u;
                ldmatrix_x4(bf[nf2], sb + sw128(off));
            }
#pragma unroll
            for (int mf = 0; mf < 4; ++mf)
#pragma unroll
                for (int nf2 = 0; nf2 < 4; ++nf2) {
                    mma16816(acc[mf][nf2 * 2],     a[mf], bf[nf2][0], bf[nf2][2]);
                    mma16816(acc[mf][nf2 * 2 + 1], a[mf], bf[nf2][1], bf[nf2][3]);
                }
        }

        if (kc == 1) {
            int jt = i >> 1;
            int colb = jbeg + jt * 256 + warp_n * 64 + 2 * (lane & 3);
#pragma unroll
            for (int mf = 0; mf < 4; ++mf) {
                int r0 = row0 + warp_m * 64 + mf * 16 + (lane >> 2);
                float m0 = rm[mf * 2], m1 = rm[mf * 2 + 1];
#pragma unroll
                for (int nf = 0; nf < 8; ++nf) {
                    float* c = acc[mf][nf];
                    int cc = colb + nf * 8;
                    __half2 h01 = __floats2half2_rn(c[0], c[1]);
                    __half2 h23 = __floats2half2_rn(c[2], c[3]);
                    *(__half2*)(sims_b + (size_t)r0 * N_ + cc)       = h01;
                    *(__half2*)(sims_b + (size_t)(r0 + 8) * N_ + cc) = h23;
                    m0 = fmaxf(m0, fmaxf(c[0], c[1]));
                    m1 = fmaxf(m1, fmaxf(c[2], c[3]));
                    c[0] = c[1] = c[2] = c[3] = 0.0f;
                }
                rm[mf * 2] = m0; rm[mf * 2 + 1] = m1;
            }
        }
        __syncthreads();
    }

#pragma unroll
    for (int j = 0; j < 8; ++j) {
        rm[j] = fmaxf(rm[j], __shfl_xor_sync(0xffffffffu, rm[j], 1));
        rm[j] = fmaxf(rm[j], __shfl_xor_sync(0xffffffffu, rm[j], 2));
    }
    float* smax = (float*)(smem + SM_MAX);
    if ((lane & 3) == 0) {
#pragma unroll
        for (int mf = 0; mf < 4; ++mf) {
            int rloc = warp_m * 64 + mf * 16 + (lane >> 2);
            smax[warp_n * 128 + rloc]     = rm[mf * 2];
            smax[warp_n * 128 + rloc + 8] = rm[mf * 2 + 1];
        }
    }
    __syncthreads();
    if (tid < 128) {
        int row = row0 + tid;
        if (row < ni) {
            float m = fmaxf(fmaxf(smax[tid], smax[128 + tid]),
                            fmaxf(smax[256 + tid], smax[384 + tid]));
            atomicMax(&g_rmax[b * N_ + row], enc_max(m));
        }
    }
}

// ---------------- rescore: vectorized gated scan + cooperative exact dots --
// 8 warps per CTA, one warp per invalid row.
__global__ __launch_bounds__(256) void rescore_kernel() {
    __shared__ unsigned short sbuf[8][264];
    __shared__ int scnt[8];
    int wl = threadIdx.x >> 5, lane = threadIdx.x & 31;
    int gw = blockIdx.x * 8 + wl;
    if (gw >= B_ * N_) return;
    int b = gw / N_, row = gw - b * N_;
    int ni = g_ninv[b], nv = g_nval[b];
    if (row >= ni || nv <= 0) return;

    float m = dec_max(g_rmax[b * N_ + row]);
    if (!(m > CONF_THRESH - GATE_SKIP)) return;  // true max certainly < 0.8
    float gate = m - GATE_CAND;

    const uint4* srow = (const uint4*)(g_sims + (size_t)b * N_ * N_
                                       + (size_t)row * N_);
    int limit = ((nv + 255) & ~255) >> 3;        // valid uint4 words in row

    const float* rf = g_Rf + ((size_t)b * N_ + row) * D_;
    float4 r0 = ((const float4*)rf)[lane];
    float4 r1 = ((const float4*)rf)[lane + 32];
    const float* vb = g_Vf + (size_t)b * N_ * D_;

    if (lane == 0) scnt[wl] = 0;
    __syncwarp();

    float best = -INFINITY;
    for (int basew = 0; basew < limit; basew += 32) {
        int wi = basew + lane;
        if (wi < limit) {
            uint4 v = srow[wi];
            int col0 = wi * 8;
            unsigned words[4] = {v.x, v.y, v.z, v.w};
#pragma unroll
            for (int h = 0; h < 4; ++h) {
                __half2 hh = *(__half2*)&words[h];
                float s0 = __low2float(hh), s1 = __high2float(hh);
                if (s0 >= gate) {
                    int i = atomicAdd(&scnt[wl], 1);
                    sbuf[wl][i] = (unsigned short)(col0 + 2 * h);
                }
                if (s1 >= gate) {
                    int i = atomicAdd(&scnt[wl], 1);
                    sbuf[wl][i] = (unsigned short)(col0 + 2 * h + 1);
                }
            }
        }
        __syncwarp();
        int cnt = scnt[wl];
        for (int c = 0; c < cnt; ++c) {
            int col = sbuf[wl][c];
            const float4* vc = (const float4*)(vb + (size_t)col * D_);
            float4 x0 = vc[lane], x1 = vc[lane + 32];
            float s = 0.0f;
            s = fmaf(x0.x, r0.x, s); s = fmaf(x0.y, r0.y, s);
            s = fmaf(x0.z, r0.z, s); s = fmaf(x0.w, r0.w, s);
            s = fmaf(x1.x, r1.x, s); s = fmaf(x1.y, r1.y, s);
            s = fmaf(x1.z, r1.z, s); s = fmaf(x1.w, r1.w, s);
#pragma unroll
            for (int o = 16; o; o >>= 1)
                s += __shfl_xor_sync(0xffffffffu, s, o);
            best = fmaxf(best, s);
        }
        __syncwarp();
        if (lane == 0) scnt[wl] = 0;
        __syncwarp();
    }
    if (lane == 0 && best > CONF_THRESH) {
        atomicAdd(&g_contrib[b], (double)(1.0f - best));
        atomicAdd(&g_nconf[b], 1);
    }
}

// ---------------- finalize ----------------
__global__ void finalize_kernel(float* out) {
    if (threadIdx.x == 0 && blockIdx.x == 0) {
        double tl = 0.0, tp = 0.0;
        for (int b = 0; b < B_; ++b) {
            int ni = g_ninv[b], nvv = g_nval[b], nc = g_nconf[b];
            bool active = (nc > 0) && (nvv > 0) && (ni > 0);
            if (active) {
                double pseudo = g_contrib[b] / (double)(nc > 1 ? nc : 1);
                tl += pseudo * (double)ni;
                tp += (double)ni;
            }
        }
        out[0] = (tp > 0.0) ? (float)(0.01 * tl / tp) : 0.0f;
    }
}

// ---------------- launch ----------------
extern "C" void kernel_launch(void* const* d_in, const int* in_sizes, int n_in,
                              void* d_out, int out_size) {
    int fi = 0, mi = 1;
    if (n_in >= 2 && in_sizes[0] < in_sizes[1]) { fi = 1; mi = 0; }
    const float* feat = (const float*)d_in[fi];
    const void*  mask = d_in[mi];

    cudaFuncSetAttribute(maxsim_p1, cudaFuncAttributeMaxDynamicSharedMemorySize,
                         SMEM_BYTES);

    init_kernel<<<(B_ * N_ + 255) / 256, 256>>>();
    detect_kernel<<<1, 1024>>>((const unsigned char*)mask);
    norm_compact_kernel<<<(B_ * N_ * 32 + 255) / 256, 256>>>(feat, mask);
    dim3 g(N_ / 128, B_, JSPLIT);
    maxsim_p1<<<g, 256, SMEM_BYTES>>>();
    rescore_kernel<<<(B_ * N_ + 7) / 8, 256>>>();
    finalize_kernel<<<1, 32>>>((float*)d_out);
}

// round 11
// speedup vs baseline: 3.2605x; 1.4245x over previous
#include <cuda_runtime.h>
#include <cuda_bf16.h>
#include <math.h>
#include <stdint.h>

// Problem constants
#define B_ 2
#define N_ 12288
#define D_ 256
#define NW (N_ / 32)            // bitmask words per row = 384
#define CONF_THRESH 0.8f
#define JSPLIT 3
// bf16 mma sim abs error bound ~0.0044:
#define CAND_T    0.7925f       // flag threshold (abs)
#define SKIP_M    0.7956f       // row skip: m <= SKIP_M => true max <= 0.8

// ---------------- device scratch (no allocations allowed) ----------------
__device__ __nv_bfloat16 g_Vhi[(size_t)B_ * N_ * D_];
__device__ __nv_bfloat16 g_Rhi[(size_t)B_ * N_ * D_];
__device__ float    g_Vf[(size_t)B_ * N_ * D_];
__device__ float    g_Rf[(size_t)B_ * N_ * D_];
__device__ unsigned g_bm[(size_t)B_ * N_ * NW];   // candidate bitmask
__device__ int      g_nval[B_];
__device__ int      g_ninv[B_];
__device__ int      g_nconf[B_];
__device__ unsigned g_rmax[B_ * N_];     // monotonic-encoded approx row max
__device__ double   g_contrib[B_];
__device__ int      g_mask_mode;         // 0=int32, 1=uint8, 2=float32

// SMEM layout (bytes):
//   A tile : [0, 65536)        = 128 rows x 256 k bf16 (32 u16B/row), SW128 atoms
//   B bufs : [65536, 196608)   = 2 buffers x (256 cols x 128 k bf16)
//   rowmax : [196608, 198656)  = 4 x 128 floats
#define SM_A    0u
#define SM_B    65536u
#define SM_MAX  196608u
#define SMEM_BYTES 198656

// ---------------- small helpers ----------------
__device__ __forceinline__ uint32_t smem_u32_addr(const void* p) {
    uint32_t a;
    asm("{ .reg .u64 t; cvta.to.shared.u64 t, %1; cvt.u32.u64 %0, t; }"
        : "=r"(a) : "l"(p));
    return a;
}
__device__ __forceinline__ uint32_t sw128(uint32_t off) {
    return off ^ ((off >> 3) & 0x70u);
}
__device__ __forceinline__ void ldmatrix_x4(uint32_t* r, uint32_t addr) {
    asm volatile("ldmatrix.sync.aligned.m8n8.x4.shared.b16 {%0,%1,%2,%3}, [%4];"
                 : "=r"(r[0]), "=r"(r[1]), "=r"(r[2]), "=r"(r[3]) : "r"(addr));
}
__device__ __forceinline__ void mma16816(float* c, const uint32_t* a,
                                         uint32_t b0, uint32_t b1) {
    asm volatile(
        "mma.sync.aligned.m16n8k16.row.col.f32.bf16.bf16.f32 "
        "{%0,%1,%2,%3}, {%4,%5,%6,%7}, {%8,%9}, {%0,%1,%2,%3};"
        : "+f"(c[0]), "+f"(c[1]), "+f"(c[2]), "+f"(c[3])
        : "r"(a[0]), "r"(a[1]), "r"(a[2]), "r"(a[3]), "r"(b0), "r"(b1));
}
__device__ __forceinline__ void cp_async16(uint32_t saddr, const void* gaddr, int sz) {
    asm volatile("cp.async.ca.shared.global [%0], [%1], 16, %2;"
                 :: "r"(saddr), "l"(gaddr), "r"(sz));
}
__device__ __forceinline__ void cp_commit() {
    asm volatile("cp.async.commit_group;");
}
template <int N>
__device__ __forceinline__ void cp_wait() {
    asm volatile("cp.async.wait_group %0;" :: "n"(N));
}
__device__ __forceinline__ unsigned enc_max(float m) {
    int rep = __float_as_int(m);
    return (rep < 0) ? ~((unsigned)rep) : ((unsigned)rep | 0x80000000u);
}
__device__ __forceinline__ float dec_max(unsigned key) {
    return (key & 0x80000000u) ? __uint_as_float(key & 0x7fffffffu)
                               : __uint_as_float(~key);
}

// ---------------- init ----------------
__global__ void init_kernel() {
    int i = blockIdx.x * blockDim.x + threadIdx.x;
    if (i < B_ * N_) g_rmax[i] = 0u;
    if (i < B_) {
        g_nval[i] = 0; g_ninv[i] = 0; g_nconf[i] = 0; g_contrib[i] = 0.0;
    }
}

// ---------------- mask dtype detection ----------------
__global__ void detect_kernel(const unsigned char* __restrict__ mraw) {
    __shared__ int s_f3f, s_foff;
    if (threadIdx.x == 0) { s_f3f = 0; s_foff = 0; }
    __syncthreads();
    int f3f = 0, foff = 0;
    for (int i = threadIdx.x; i < B_ * N_; i += blockDim.x) {
        unsigned char c = mraw[i];
        if ((i & 3) == 3 && c == 0x3f) f3f = 1;
        if ((i & 3) != 0 && c != 0)    foff = 1;
    }
    if (f3f)  atomicOr(&s_f3f, 1);
    if (foff) atomicOr(&s_foff, 1);
    __syncthreads();
    if (threadIdx.x == 0) g_mask_mode = s_f3f ? 2 : (s_foff ? 1 : 0);
}

// ---------------- normalize + compact (one warp per point) ----------------
__global__ void norm_compact_kernel(const float* __restrict__ feat,
                                    const void*  __restrict__ mraw) {
    int gw   = (int)((blockIdx.x * blockDim.x + threadIdx.x) >> 5);
    int lane = threadIdx.x & 31;
    if (gw >= B_ * N_) return;
    int b = gw / N_;

    int mv = 0;
    if (lane == 0) {
        int mode = g_mask_mode;
        if (mode == 0)      mv = (((const int*)mraw)[gw] != 0);
        else if (mode == 1) mv = (((const unsigned char*)mraw)[gw] != 0);
        else                mv = (((const float*)mraw)[gw] != 0.0f);
    }
    mv = __shfl_sync(0xffffffffu, mv, 0);

    const float* src = feat + (size_t)gw * D_;
    float4 v0 = ((const float4*)src)[lane];
    float4 v1 = ((const float4*)src)[lane + 32];
    float ss = v0.x * v0.x + v0.y * v0.y + v0.z * v0.z + v0.w * v0.w
             + v1.x * v1.x + v1.y * v1.y + v1.z * v1.z + v1.w * v1.w;
#pragma unroll
    for (int o = 16; o; o >>= 1) ss += __shfl_xor_sync(0xffffffffu, ss, o);
    float inv = 1.0f / fmaxf(sqrtf(ss), 1e-12f);
    v0.x *= inv; v0.y *= inv; v0.z *= inv; v0.w *= inv;
    v1.x *= inv; v1.y *= inv; v1.z *= inv; v1.w *= inv;

    int slot = 0;
    if (lane == 0)
        slot = atomicAdd(mv ? &g_nval[b] : &g_ninv[b], 1);
    slot = __shfl_sync(0xffffffffu, slot, 0);

    size_t base = ((size_t)b * N_ + slot) * D_;
    __nv_bfloat16* dh = (mv ? g_Vhi : g_Rhi) + base;
    float*         df = (mv ? g_Vf  : g_Rf)  + base;

    __nv_bfloat162 h0 = __floats2bfloat162_rn(v0.x, v0.y);
    __nv_bfloat162 h1 = __floats2bfloat162_rn(v0.z, v0.w);
    uint2 h; h.x = *(uint32_t*)&h0; h.y = *(uint32_t*)&h1;
    ((uint2*)dh)[lane] = h;
    h0 = __floats2bfloat162_rn(v1.x, v1.y);
    h1 = __floats2bfloat162_rn(v1.z, v1.w);
    h.x = *(uint32_t*)&h0; h.y = *(uint32_t*)&h1;
    ((uint2*)dh)[32 + lane] = h;
    ((float4*)df)[lane]      = v0;
    ((float4*)df)[lane + 32] = v1;
}

// ---------------- pass 1: approx bf16 HMMA -> row max + candidate bitmask --
// grid (N_/128, B_, JSPLIT), 256 threads (8 warps: 2 m-warps x 4 n-warps,
// warp tile 64x64). CTA tile 128 rows x 256 cols. Each CTA owns a DISJOINT
// bitmask word range (plain STG, no atomics, no init needed).
__global__ __launch_bounds__(256, 1) void maxsim_p1() {
    extern __shared__ __align__(1024) char smem[];
    int b = blockIdx.y;
    int ni = g_ninv[b], nv = g_nval[b];
    int row0 = blockIdx.x * 128;
    if (row0 >= ni || nv <= 0) return;

    int tiles_total = (nv + 255) >> 8;
    int tiles_per   = (tiles_total + JSPLIT - 1) / JSPLIT;
    int jbeg = blockIdx.z * tiles_per * 256;
    int jend = min(nv, jbeg + tiles_per * 256);
    if (jbeg >= jend) return;

    uint32_t sb = smem_u32_addr(smem);
    int tid = threadIdx.x;
    int lane = tid & 31, warp = tid >> 5;
    int warp_m = warp & 1, warp_n = warp >> 1;   // 2 x 4 warp grid

    const __nv_bfloat16* Rhi_b = g_Rhi + (size_t)b * N_ * D_;
    const __nv_bfloat16* Vhi_b = g_Vhi + (size_t)b * N_ * D_;
    unsigned* bm_b = g_bm + (size_t)b * N_ * NW;

#pragma unroll
    for (int it = 0; it < 16; ++it) {
        int u = tid + it * 256;
        int row = u >> 5;
        int ku  = u & 31;
        int gr  = min(row0 + row, ni - 1);
        const uint4* src = (const uint4*)(Rhi_b + (size_t)gr * D_) + ku;
        uint32_t off = SM_A
                     + (uint32_t)((row >> 3) * 4 + (ku >> 3)) * 1024u
                     + (uint32_t)(row & 7) * 128u + (uint32_t)(ku & 7) * 16u;
        *(uint4*)(smem + sw128(off)) = *src;
    }

    float acc[4][8][4];
#pragma unroll
    for (int mf = 0; mf < 4; ++mf)
#pragma unroll
        for (int nf = 0; nf < 8; ++nf)
#pragma unroll
            for (int q = 0; q < 4; ++q) acc[mf][nf][q] = 0.0f;
    float rm[8];
#pragma unroll
    for (int r = 0; r < 8; ++r) rm[r] = -INFINITY;

    int Tj = (jend - jbeg + 255) >> 8;
    int NC = Tj * 2;

    auto cp_chunk = [&](int c, int bufsel) {
        int jt = c >> 1, kc = c & 1;
        int col0 = jbeg + jt * 256;
#pragma unroll
        for (int i = 0; i < 16; ++i) {
            int u = tid + i * 256;
            int col = u >> 4;
            int ku  = u & 15;
            int gc  = col0 + col;
            const void* src = (const void*)(Vhi_b + (size_t)gc * D_ + kc * 128 + ku * 8);
            uint32_t off = SM_B + (uint32_t)bufsel * 65536u
                         + (uint32_t)((col >> 3) * 2 + (ku >> 3)) * 1024u
                         + (uint32_t)(col & 7) * 128u + (uint32_t)(ku & 7) * 16u;
            cp_async16(sb + sw128(off), src, (gc < jend) ? 16 : 0);
        }
        cp_commit();
    };

    cp_chunk(0, 0);
    __syncthreads();

    for (int i = 0; i < NC; ++i) {
        int bufsel = i & 1;
        int kc = i & 1;
        if (i + 1 < NC) { cp_chunk(i + 1, (i + 1) & 1); cp_wait<1>(); }
        else            { cp_wait<0>(); }
        __syncthreads();

#pragma unroll
        for (int kk = 0; kk < 8; ++kk) {
            uint32_t a[4][4];
#pragma unroll
            for (int mf = 0; mf < 4; ++mf) {
                int row = warp_m * 64 + mf * 16 + (lane & 15);
                int ku  = (kc * 8 + kk) * 2 + (lane >> 4);
                uint32_t off = SM_A
                             + (uint32_t)((row >> 3) * 4 + (ku >> 3)) * 1024u
                             + (uint32_t)(row & 7) * 128u
                             + (uint32_t)(ku & 7) * 16u;
                ldmatrix_x4(a[mf], sb + sw128(off));
            }
            uint32_t bf[4][4];
#pragma unroll
            for (int nf2 = 0; nf2 < 4; ++nf2) {
                int col = warp_n * 64 + nf2 * 16 + (lane & 15);
                int ku  = kk * 2 + (lane >> 4);
                uint32_t off = SM_B + (uint32_t)bufsel * 65536u
                             + (uint32_t)((col >> 3) * 2 + (ku >> 3)) * 1024u
                             + (uint32_t)(col & 7) * 128u
                             + (uint32_t)(ku & 7) * 16u;
                ldmatrix_x4(bf[nf2], sb + sw128(off));
            }
#pragma unroll
            for (int mf = 0; mf < 4; ++mf)
#pragma unroll
                for (int nf2 = 0; nf2 < 4; ++nf2) {
                    mma16816(acc[mf][nf2 * 2],     a[mf], bf[nf2][0], bf[nf2][2]);
                    mma16816(acc[mf][nf2 * 2 + 1], a[mf], bf[nf2][1], bf[nf2][3]);
                }
        }

        if (kc == 1) {
            // end of j-tile: build candidate bits + fold row max, reset accs.
            int jt = i >> 1;
            int wbase = (jbeg + jt * 256 + warp_n * 64) >> 5;  // 2 words/warp
            int shl = 2 * (lane & 3);
#pragma unroll
            for (int mf = 0; mf < 4; ++mf) {
                float m0 = rm[mf * 2], m1 = rm[mf * 2 + 1];
#pragma unroll
                for (int rp = 0; rp < 2; ++rp) {
                    unsigned w0 = 0u, w1 = 0u;
#pragma unroll
                    for (int nf = 0; nf < 8; ++nf) {
                        float c0 = acc[mf][nf][rp * 2];
                        float c1 = acc[mf][nf][rp * 2 + 1];
                        unsigned bits = (c0 > CAND_T ? 1u : 0u)
                                      | (c1 > CAND_T ? 2u : 0u);
                        bits <<= ((nf & 3) * 8 + shl);
                        if (nf < 4) w0 |= bits; else w1 |= bits;
                        float mm = fmaxf(c0, c1);
                        if (rp == 0) m0 = fmaxf(m0, mm);
                        else         m1 = fmaxf(m1, mm);
                    }
                    w0 |= __shfl_xor_sync(0xffffffffu, w0, 1);
                    w0 |= __shfl_xor_sync(0xffffffffu, w0, 2);
                    w1 |= __shfl_xor_sync(0xffffffffu, w1, 1);
                    w1 |= __shfl_xor_sync(0xffffffffu, w1, 2);
                    int r = row0 + warp_m * 64 + mf * 16 + (lane >> 2) + rp * 8;
                    if ((lane & 3) == 0 && r < ni) {
                        unsigned* dst = bm_b + (size_t)r * NW + wbase;
                        dst[0] = w0;
                        dst[1] = w1;
                    }
                }
#pragma unroll
                for (int nf = 0; nf < 8; ++nf)
#pragma unroll
                    for (int q = 0; q < 4; ++q) acc[mf][nf][q] = 0.0f;
                rm[mf * 2] = m0; rm[mf * 2 + 1] = m1;
            }
        }
        __syncthreads();
    }

#pragma unroll
    for (int j = 0; j < 8; ++j) {
        rm[j] = fmaxf(rm[j], __shfl_xor_sync(0xffffffffu, rm[j], 1));
        rm[j] = fmaxf(rm[j], __shfl_xor_sync(0xffffffffu, rm[j], 2));
    }
    float* smax = (float*)(smem + SM_MAX);
    if ((lane & 3) == 0) {
#pragma unroll
        for (int mf = 0; mf < 4; ++mf) {
            int rloc = warp_m * 64 + mf * 16 + (lane >> 2);
            smax[warp_n * 128 + rloc]     = rm[mf * 2];
            smax[warp_n * 128 + rloc + 8] = rm[mf * 2 + 1];
        }
    }
    __syncthreads();
    if (tid < 128) {
        int row = row0 + tid;
        if (row < ni) {
            float m = fmaxf(fmaxf(smax[tid], smax[128 + tid]),
                            fmaxf(smax[256 + tid], smax[384 + tid]));
            atomicMax(&g_rmax[b * N_ + row], enc_max(m));
        }
    }
}

// ---------------- rescore: bitmask scan + cooperative exact fp32 dots ------
// 8 warps per CTA, one warp per invalid row.
__global__ __launch_bounds__(256) void rescore_kernel() {
    __shared__ unsigned short sbuf[8][1056];
    __shared__ int scnt[8];
    int wl = threadIdx.x >> 5, lane = threadIdx.x & 31;
    int gw = blockIdx.x * 8 + wl;
    if (gw >= B_ * N_) return;
    int b = gw / N_, row = gw - b * N_;
    int ni = g_ninv[b], nv = g_nval[b];
    if (row >= ni || nv <= 0) return;

    float m = dec_max(g_rmax[b * N_ + row]);
    if (!(m > SKIP_M)) return;   // true max certainly <= 0.8

    const unsigned* bmr = g_bm + ((size_t)b * N_ + row) * NW;
    int limit_w = (nv + 31) >> 5;

    const float* rf = g_Rf + ((size_t)b * N_ + row) * D_;
    float4 r0 = ((const float4*)rf)[lane];
    float4 r1 = ((const float4*)rf)[lane + 32];
    const float* vb = g_Vf + (size_t)b * N_ * D_;

    if (lane == 0) scnt[wl] = 0;
    __syncwarp();

    float best = -INFINITY;
    for (int basew = 0; basew < limit_w; basew += 32) {
        int wi = basew + lane;
        unsigned w = (wi < limit_w) ? bmr[wi] : 0u;
        while (w) {
            int bit = __ffs(w) - 1;
            w &= w - 1;
            int i = atomicAdd(&scnt[wl], 1);
            sbuf[wl][i] = (unsigned short)(wi * 32 + bit);
        }
        __syncwarp();
        int cnt = scnt[wl];
        for (int c = 0; c < cnt; ++c) {
            int col = sbuf[wl][c];
            const float4* vc = (const float4*)(vb + (size_t)col * D_);
            float4 x0 = vc[lane], x1 = vc[lane + 32];
            float s = 0.0f;
            s = fmaf(x0.x, r0.x, s); s = fmaf(x0.y, r0.y, s);
            s = fmaf(x0.z, r0.z, s); s = fmaf(x0.w, r0.w, s);
            s = fmaf(x1.x, r1.x, s); s = fmaf(x1.y, r1.y, s);
            s = fmaf(x1.z, r1.z, s); s = fmaf(x1.w, r1.w, s);
#pragma unroll
            for (int o = 16; o; o >>= 1)
                s += __shfl_xor_sync(0xffffffffu, s, o);
            best = fmaxf(best, s);
        }
        __syncwarp();
        if (lane == 0) scnt[wl] = 0;
        __syncwarp();
    }
    if (lane == 0 && best > CONF_THRESH) {
        atomicAdd(&g_contrib[b], (double)(1.0f - best));
        atomicAdd(&g_nconf[b], 1);
    }
}

// ---------------- finalize ----------------
__global__ void finalize_kernel(float* out) {
    if (threadIdx.x == 0 && blockIdx.x == 0) {
        double tl = 0.0, tp = 0.0;
        for (int b = 0; b < B_; ++b) {
            int ni = g_ninv[b], nvv = g_nval[b], nc = g_nconf[b];
            bool active = (nc > 0) && (nvv > 0) && (ni > 0);
            if (active) {
                double pseudo = g_contrib[b] / (double)(nc > 1 ? nc : 1);
                tl += pseudo * (double)ni;
                tp += (double)ni;
            }
        }
        out[0] = (tp > 0.0) ? (float)(0.01 * tl / tp) : 0.0f;
    }
}

// ---------------- launch ----------------
extern "C" void kernel_launch(void* const* d_in, const int* in_sizes, int n_in,
                              void* d_out, int out_size) {
    int fi = 0, mi = 1;
    if (n_in >= 2 && in_sizes[0] < in_sizes[1]) { fi = 1; mi = 0; }
    const float* feat = (const float*)d_in[fi];
    const void*  mask = d_in[mi];

    cudaFuncSetAttribute(maxsim_p1, cudaFuncAttributeMaxDynamicSharedMemorySize,
                         SMEM_BYTES);

    init_kernel<<<(B_ * N_ + 255) / 256, 256>>>();
    detect_kernel<<<1, 1024>>>((const unsigned char*)mask);
    norm_compact_kernel<<<(B_ * N_ * 32 + 255) / 256, 256>>>(feat, mask);
    dim3 g(N_ / 128, B_, JSPLIT);
    maxsim_p1<<<g, 256, SMEM_BYTES>>>();
    rescore_kernel<<<(B_ * N_ + 7) / 8, 256>>>();
    finalize_kernel<<<1, 32>>>((float*)d_out);
}

// round 12
// speedup vs baseline: 3.5403x; 1.0858x over previous
#include <cuda_runtime.h>
#include <cuda_bf16.h>
#include <math.h>
#include <stdint.h>

// Problem constants
#define B_ 2
#define N_ 12288
#define D_ 256
#define NW (N_ / 32)            // bitmask words per row = 384
#define NT (N_ / 128)           // 128-wide tiles per batch = 96
#define CONF_THRESH 0.8f
#define JSPLIT 3
// bf16 mma sim abs error bound ~0.0044:
#define CAND_T    0.7925f       // flag threshold (abs)
#define SKIP_M    0.7956f       // row skip: m <= SKIP_M => true max <= 0.8

// ---------------- device scratch (no allocations allowed) ----------------
// Tiled bf16 images: per 128-point tile, 64KB laid out exactly as the SMEM
// image (SW128 atoms), so one cp.async.bulk reproduces it in SMEM.
__device__ __align__(128) uint4 g_Vt[(size_t)B_ * NT * 4096];
__device__ __align__(128) uint4 g_Rt[(size_t)B_ * NT * 4096];
__device__ float    g_Vf[(size_t)B_ * N_ * D_];
__device__ float    g_Rf[(size_t)B_ * N_ * D_];
__device__ unsigned g_bm[(size_t)B_ * N_ * NW];   // candidate bitmask
__device__ int      g_nval[B_];
__device__ int      g_ninv[B_];
__device__ int      g_nconf[B_];
__device__ unsigned g_rmax[B_ * N_];     // monotonic-encoded approx row max
__device__ double   g_contrib[B_];
__device__ int      g_mask_mode;         // 0=int32, 1=uint8, 2=float32

// SMEM layout (bytes):
//   A tile : [0, 65536)        = 128 rows x 256 k bf16, SW128 atom image
//   B bufs : [65536, 196608)   = 2 x (128 cols x 256 k bf16) images
//   rowmax : [196608, 198656)  = 4 x 128 floats
//   mbars  : [198656, 198680)  = 3 x 8B
#define SM_A    0u
#define SM_B    65536u
#define SM_MAX  196608u
#define SM_MBAR 198656u
#define SMEM_BYTES 198720

// ---------------- small helpers ----------------
__device__ __forceinline__ uint32_t smem_u32_addr(const void* p) {
    uint32_t a;
    asm("{ .reg .u64 t; cvta.to.shared.u64 t, %1; cvt.u32.u64 %0, t; }"
        : "=r"(a) : "l"(p));
    return a;
}
__device__ __forceinline__ uint32_t sw128(uint32_t off) {
    return off ^ ((off >> 3) & 0x70u);
}
// tile-image byte offset for (point c, 16B-unit ku), c in [0,128), ku in [0,32)
__device__ __forceinline__ uint32_t img_off(int c, int ku) {
    return (uint32_t)((c >> 3) * 4 + (ku >> 3)) * 1024u
         + (uint32_t)(c & 7) * 128u + (uint32_t)(ku & 7) * 16u;
}
__device__ __forceinline__ void ldmatrix_x4(uint32_t* r, uint32_t addr) {
    asm volatile("ldmatrix.sync.aligned.m8n8.x4.shared.b16 {%0,%1,%2,%3}, [%4];"
                 : "=r"(r[0]), "=r"(r[1]), "=r"(r[2]), "=r"(r[3]) : "r"(addr));
}
__device__ __forceinline__ void mma16816(float* c, const uint32_t* a,
                                         uint32_t b0, uint32_t b1) {
    asm volatile(
        "mma.sync.aligned.m16n8k16.row.col.f32.bf16.bf16.f32 "
        "{%0,%1,%2,%3}, {%4,%5,%6,%7}, {%8,%9}, {%0,%1,%2,%3};"
        : "+f"(c[0]), "+f"(c[1]), "+f"(c[2]), "+f"(c[3])
        : "r"(a[0]), "r"(a[1]), "r"(a[2]), "r"(a[3]), "r"(b0), "r"(b1));
}
#define MBAR_INIT(mbar, cnt) \
    asm volatile("mbarrier.init.shared.b64 [%0], %1;" \
                 :: "r"(mbar), "r"((uint32_t)(cnt)) : "memory")
#define MBAR_EXPECT_TX(mbar, tx) \
    asm volatile("mbarrier.arrive.expect_tx.shared.b64 _, [%0], %1;" \
                 :: "r"(mbar), "r"((uint32_t)(tx)) : "memory")
__device__ __forceinline__ void bulk_ldg(uint32_t sdst, const void* gsrc,
                                         uint32_t bytes, uint32_t mbar) {
    asm volatile(
        "cp.async.bulk.shared::cluster.global.mbarrier::complete_tx::bytes "
        "[%0], [%1], %2, [%3];"
        :: "r"(sdst), "l"(gsrc), "r"(bytes), "r"(mbar) : "memory");
}
#define MBAR_WAIT_PARITY(mbar, par) do {                                           \
    uint32_t _m = (mbar); uint32_t _p = (uint32_t)(par); uint32_t _d;              \
    asm volatile("{ .reg .pred p; "                                                \
        "mbarrier.try_wait.parity.acquire.cta.shared::cta.b64 p, [%1], %2; "       \
        "selp.b32 %0, 1, 0, p; }" : "=r"(_d) : "r"(_m), "r"(_p) : "memory");       \
    if (!_d) {                                                                     \
        asm volatile("{ .reg .pred P1; "                                           \
            "WL_%=: mbarrier.try_wait.parity.acquire.cta.shared::cta.b64 P1, [%0], %1, 0x989680; " \
            "@P1 bra.uni WD_%=; bra.uni WL_%=; WD_%=: }"                           \
            :: "r"(_m), "r"(_p) : "memory");                                       \
    }                                                                              \
} while (0)
__device__ __forceinline__ unsigned enc_max(float m) {
    int rep = __float_as_int(m);
    return (rep < 0) ? ~((unsigned)rep) : ((unsigned)rep | 0x80000000u);
}
__device__ __forceinline__ float dec_max(unsigned key) {
    return (key & 0x80000000u) ? __uint_as_float(key & 0x7fffffffu)
                               : __uint_as_float(~key);
}

// ---------------- init ----------------
__global__ void init_kernel() {
    int i = blockIdx.x * blockDim.x + threadIdx.x;
    if (i < B_ * N_) g_rmax[i] = 0u;
    if (i < B_) {
        g_nval[i] = 0; g_ninv[i] = 0; g_nconf[i] = 0; g_contrib[i] = 0.0;
    }
}

// zero the tile images (tail tiles must read as sim=0)
__global__ void zero_tiles_kernel() {
    size_t i = (size_t)blockIdx.x * blockDim.x + threadIdx.x;
    size_t total = (size_t)B_ * NT * 4096;
    uint4 z = make_uint4(0u, 0u, 0u, 0u);
    for (; i < total; i += (size_t)gridDim.x * blockDim.x) {
        g_Vt[i] = z;
        g_Rt[i] = z;
    }
}

// ---------------- mask dtype detection ----------------
__global__ void detect_kernel(const unsigned char* __restrict__ mraw) {
    __shared__ int s_f3f, s_foff;
    if (threadIdx.x == 0) { s_f3f = 0; s_foff = 0; }
    __syncthreads();
    int f3f = 0, foff = 0;
    for (int i = threadIdx.x; i < B_ * N_; i += blockDim.x) {
        unsigned char c = mraw[i];
        if ((i & 3) == 3 && c == 0x3f) f3f = 1;
        if ((i & 3) != 0 && c != 0)    foff = 1;
    }
    if (f3f)  atomicOr(&s_f3f, 1);
    if (foff) atomicOr(&s_foff, 1);
    __syncthreads();
    if (threadIdx.x == 0) g_mask_mode = s_f3f ? 2 : (s_foff ? 1 : 0);
}

// ---------------- normalize + compact (one warp per point) ----------------
// Writes bf16 into tiled SW128 images (for bulk-copy MMA) and fp32 linear
// (for exact rescore).
__global__ void norm_compact_kernel(const float* __restrict__ feat,
                                    const void*  __restrict__ mraw) {
    int gw   = (int)((blockIdx.x * blockDim.x + threadIdx.x) >> 5);
    int lane = threadIdx.x & 31;
    if (gw >= B_ * N_) return;
    int b = gw / N_;

    int mv = 0;
    if (lane == 0) {
        int mode = g_mask_mode;
        if (mode == 0)      mv = (((const int*)mraw)[gw] != 0);
        else if (mode == 1) mv = (((const unsigned char*)mraw)[gw] != 0);
        else                mv = (((const float*)mraw)[gw] != 0.0f);
    }
    mv = __shfl_sync(0xffffffffu, mv, 0);

    const float* src = feat + (size_t)gw * D_;
    float4 v0 = ((const float4*)src)[lane];
    float4 v1 = ((const float4*)src)[lane + 32];
    float ss = v0.x * v0.x + v0.y * v0.y + v0.z * v0.z + v0.w * v0.w
             + v1.x * v1.x + v1.y * v1.y + v1.z * v1.z + v1.w * v1.w;
#pragma unroll
    for (int o = 16; o; o >>= 1) ss += __shfl_xor_sync(0xffffffffu, ss, o);
    float inv = 1.0f / fmaxf(sqrtf(ss), 1e-12f);
    v0.x *= inv; v0.y *= inv; v0.z *= inv; v0.w *= inv;
    v1.x *= inv; v1.y *= inv; v1.z *= inv; v1.w *= inv;

    int slot = 0;
    if (lane == 0)
        slot = atomicAdd(mv ? &g_nval[b] : &g_ninv[b], 1);
    slot = __shfl_sync(0xffffffffu, slot, 0);

    // fp32 linear
    float* df = (mv ? g_Vf : g_Rf) + ((size_t)b * N_ + slot) * D_;
    ((float4*)df)[lane]      = v0;
    ((float4*)df)[lane + 32] = v1;

    // bf16 tiled image: point c within tile, lane l holds elems 4l..4l+3 and
    // 128+4l..128+4l+3 -> halves of units (l>>1) and 16+(l>>1).
    char* img = (char*)((mv ? g_Vt : g_Rt)
                + ((size_t)b * NT + (slot >> 7)) * 4096);
    int c = slot & 127;
    __nv_bfloat162 p0 = __floats2bfloat162_rn(v0.x, v0.y);
    __nv_bfloat162 p1 = __floats2bfloat162_rn(v0.z, v0.w);
    uint2 h; h.x = *(uint32_t*)&p0; h.y = *(uint32_t*)&p1;
    uint32_t o0 = sw128(img_off(c, lane >> 1)) + (uint32_t)(lane & 1) * 8u;
    *(uint2*)(img + o0) = h;
    p0 = __floats2bfloat162_rn(v1.x, v1.y);
    p1 = __floats2bfloat162_rn(v1.z, v1.w);
    h.x = *(uint32_t*)&p0; h.y = *(uint32_t*)&p1;
    uint32_t o1 = sw128(img_off(c, 16 + (lane >> 1))) + (uint32_t)(lane & 1) * 8u;
    *(uint2*)(img + o1) = h;
}

// ---------------- pass 1: bulk-copy bf16 HMMA -> row max + candidate bits --
// grid (N_/128, B_, JSPLIT), 256 threads (8 warps: 2 m x 4 n, warp tile
// 64x32). CTA tile 128 rows x 128 cols x K256. B tiles arrive via ONE
// cp.async.bulk (64KB) each, double buffered via mbarriers.
__global__ __launch_bounds__(256, 1) void maxsim_p1() {
    extern __shared__ __align__(1024) char smem[];
    int b = blockIdx.y;
    int ni = g_ninv[b], nv = g_nval[b];
    int row0 = blockIdx.x * 128;
    if (row0 >= ni || nv <= 0) return;

    int tiles_total = (nv + 127) >> 7;
    int tiles_per   = (tiles_total + JSPLIT - 1) / JSPLIT;
    int jt0 = blockIdx.z * tiles_per;
    int jt1 = min(tiles_total, jt0 + tiles_per);
    if (jt0 >= jt1) return;
    int T = jt1 - jt0;

    uint32_t sb = smem_u32_addr(smem);
    uint32_t mbA  = sb + SM_MBAR;
    uint32_t mbB0 = sb + SM_MBAR + 8;
    uint32_t mbB1 = sb + SM_MBAR + 16;
    int tid = threadIdx.x;
    int lane = tid & 31, warp = tid >> 5;
    int warp_m = warp & 1, warp_n = warp >> 1;   // 2 x 4 warp grid

    const char* Rt_b = (const char*)(g_Rt + ((size_t)b * NT + (row0 >> 7)) * 4096);
    const char* Vt_b = (const char*)(g_Vt + (size_t)b * NT * 4096);
    unsigned* bm_b = g_bm + (size_t)b * N_ * NW;

    if (tid == 0) {
        MBAR_INIT(mbA, 1);
        MBAR_INIT(mbB0, 1);
        MBAR_INIT(mbB1, 1);
        MBAR_EXPECT_TX(mbA, 65536);
        bulk_ldg(sb + SM_A, Rt_b, 65536, mbA);
        MBAR_EXPECT_TX(mbB0, 65536);
        bulk_ldg(sb + SM_B, Vt_b + (size_t)jt0 * 65536, 65536, mbB0);
    }
    __syncthreads();
    MBAR_WAIT_PARITY(mbA, 0);

    float acc[4][4][4];
#pragma unroll
    for (int mf = 0; mf < 4; ++mf)
#pragma unroll
        for (int nf = 0; nf < 4; ++nf)
#pragma unroll
            for (int q = 0; q < 4; ++q) acc[mf][nf][q] = 0.0f;
    float rm[8];
#pragma unroll
    for (int r = 0; r < 8; ++r) rm[r] = -INFINITY;

    int ph[2] = {0, 0};

    for (int t = 0; t < T; ++t) {
        int sel = t & 1;
        if (t + 1 < T && tid == 0) {
            uint32_t mbn = ((t + 1) & 1) ? mbB1 : mbB0;
            MBAR_EXPECT_TX(mbn, 65536);
            bulk_ldg(sb + SM_B + (uint32_t)((t + 1) & 1) * 65536u,
                     Vt_b + (size_t)(jt0 + t + 1) * 65536, 65536, mbn);
        }
        MBAR_WAIT_PARITY(sel ? mbB1 : mbB0, ph[sel]);
        ph[sel] ^= 1;
        uint32_t bbase = sb + SM_B + (uint32_t)sel * 65536u;

#pragma unroll
        for (int kk = 0; kk < 16; ++kk) {
            int ku = kk * 2 + (lane >> 4);
            uint32_t a[4][4];
#pragma unroll
            for (int mf = 0; mf < 4; ++mf) {
                int row = warp_m * 64 + mf * 16 + (lane & 15);
                ldmatrix_x4(a[mf], sb + SM_A + sw128(img_off(row, ku)));
            }
            uint32_t bf[2][4];
#pragma unroll
            for (int nf2 = 0; nf2 < 2; ++nf2) {
                int col = warp_n * 32 + nf2 * 16 + (lane & 15);
                ldmatrix_x4(bf[nf2], bbase + sw128(img_off(col, ku)));
            }
#pragma unroll
            for (int mf = 0; mf < 4; ++mf)
#pragma unroll
                for (int nf2 = 0; nf2 < 2; ++nf2) {
                    mma16816(acc[mf][nf2 * 2],     a[mf], bf[nf2][0], bf[nf2][2]);
                    mma16816(acc[mf][nf2 * 2 + 1], a[mf], bf[nf2][1], bf[nf2][3]);
                }
        }

        // epilogue: candidate bits (1 word per warp, 32 cols) + row max
        {
            int jt = jt0 + t;
            int wi = (jt * 128 + warp_n * 32) >> 5;
            int shl = 2 * (lane & 3);
#pragma unroll
            for (int mf = 0; mf < 4; ++mf) {
#pragma unroll
                for (int rp = 0; rp < 2; ++rp) {
                    unsigned w = 0u;
                    float mm = -INFINITY;
#pragma unroll
                    for (int nf = 0; nf < 4; ++nf) {
                        float c0 = acc[mf][nf][rp * 2];
                        float c1 = acc[mf][nf][rp * 2 + 1];
                        unsigned bits = (c0 > CAND_T ? 1u : 0u)
                                      | (c1 > CAND_T ? 2u : 0u);
                        w |= bits << (nf * 8 + shl);
                        mm = fmaxf(mm, fmaxf(c0, c1));
                    }
                    w |= __shfl_xor_sync(0xffffffffu, w, 1);
                    w |= __shfl_xor_sync(0xffffffffu, w, 2);
                    int r = row0 + warp_m * 64 + mf * 16 + (lane >> 2) + rp * 8;
                    if ((lane & 3) == 0 && r < ni)
                        bm_b[(size_t)r * NW + wi] = w;
                    rm[mf * 2 + rp] = fmaxf(rm[mf * 2 + rp], mm);
                }
#pragma unroll
                for (int nf = 0; nf < 4; ++nf)
#pragma unroll
                    for (int q = 0; q < 4; ++q) acc[mf][nf][q] = 0.0f;
            }
        }
        __syncthreads();   // buffer sel free for reload
    }

    // reduce row maxima across lane quads, then across the 4 n-warps
#pragma unroll
    for (int j = 0; j < 8; ++j) {
        rm[j] = fmaxf(rm[j], __shfl_xor_sync(0xffffffffu, rm[j], 1));
        rm[j] = fmaxf(rm[j], __shfl_xor_sync(0xffffffffu, rm[j], 2));
    }
    float* smax = (float*)(smem + SM_MAX);
    if ((lane & 3) == 0) {
#pragma unroll
        for (int mf = 0; mf < 4; ++mf) {
            int rloc = warp_m * 64 + mf * 16 + (lane >> 2);
            smax[warp_n * 128 + rloc]     = rm[mf * 2];
            smax[warp_n * 128 + rloc + 8] = rm[mf * 2 + 1];
        }
    }
    __syncthreads();
    if (tid < 128) {
        int row = row0 + tid;
        if (row < ni) {
            float m = fmaxf(fmaxf(smax[tid], smax[128 + tid]),
                            fmaxf(smax[256 + tid], smax[384 + tid]));
            atomicMax(&g_rmax[b * N_ + row], enc_max(m));
        }
    }
}

// ---------------- rescore: bitmask scan + cooperative exact fp32 dots ------
// 8 warps per CTA, one warp per invalid row.
__global__ __launch_bounds__(256) void rescore_kernel() {
    __shared__ unsigned short sbuf[8][1056];
    __shared__ int scnt[8];
    int wl = threadIdx.x >> 5, lane = threadIdx.x & 31;
    int gw = blockIdx.x * 8 + wl;
    if (gw >= B_ * N_) return;
    int b = gw / N_, row = gw - b * N_;
    int ni = g_ninv[b], nv = g_nval[b];
    if (row >= ni || nv <= 0) return;

    float m = dec_max(g_rmax[b * N_ + row]);
    if (!(m > SKIP_M)) return;   // true max certainly <= 0.8

    const unsigned* bmr = g_bm + ((size_t)b * N_ + row) * NW;
    int limit_w = (nv + 31) >> 5;

    const float* rf = g_Rf + ((size_t)b * N_ + row) * D_;
    float4 r0 = ((const float4*)rf)[lane];
    float4 r1 = ((const float4*)rf)[lane + 32];
    const float* vb = g_Vf + (size_t)b * N_ * D_;

    if (lane == 0) scnt[wl] = 0;
    __syncwarp();

    float best = -INFINITY;
    for (int basew = 0; basew < limit_w; basew += 32) {
        int wi = basew + lane;
        unsigned w = (wi < limit_w) ? bmr[wi] : 0u;
        while (w) {
            int bit = __ffs(w) - 1;
            w &= w - 1;
            int i = atomicAdd(&scnt[wl], 1);
            sbuf[wl][i] = (unsigned short)(wi * 32 + bit);
        }
        __syncwarp();
        int cnt = scnt[wl];
        for (int c = 0; c < cnt; ++c) {
            int col = sbuf[wl][c];
            const float4* vc = (const float4*)(vb + (size_t)col * D_);
            float4 x0 = vc[lane], x1 = vc[lane + 32];
            float s = 0.0f;
            s = fmaf(x0.x, r0.x, s); s = fmaf(x0.y, r0.y, s);
            s = fmaf(x0.z, r0.z, s); s = fmaf(x0.w, r0.w, s);
            s = fmaf(x1.x, r1.x, s); s = fmaf(x1.y, r1.y, s);
            s = fmaf(x1.z, r1.z, s); s = fmaf(x1.w, r1.w, s);
#pragma unroll
            for (int o = 16; o; o >>= 1)
                s += __shfl_xor_sync(0xffffffffu, s, o);
            best = fmaxf(best, s);
        }
        __syncwarp();
        if (lane == 0) scnt[wl] = 0;
        __syncwarp();
    }
    if (lane == 0 && best > CONF_THRESH) {
        atomicAdd(&g_contrib[b], (double)(1.0f - best));
        atomicAdd(&g_nconf[b], 1);
    }
}

// ---------------- finalize ----------------
__global__ void finalize_kernel(float* out) {
    if (threadIdx.x == 0 && blockIdx.x == 0) {
        double tl = 0.0, tp = 0.0;
        for (int b = 0; b < B_; ++b) {
            int ni = g_ninv[b], nvv = g_nval[b], nc = g_nconf[b];
            bool active = (nc > 0) && (nvv > 0) && (ni > 0);
            if (active) {
                double pseudo = g_contrib[b] / (double)(nc > 1 ? nc : 1);
                tl += pseudo * (double)ni;
                tp += (double)ni;
            }
        }
        out[0] = (tp > 0.0) ? (float)(0.01 * tl / tp) : 0.0f;
    }
}

// ---------------- launch ----------------
extern "C" void kernel_launch(void* const* d_in, const int* in_sizes, int n_in,
                              void* d_out, int out_size) {
    int fi = 0, mi = 1;
    if (n_in >= 2 && in_sizes[0] < in_sizes[1]) { fi = 1; mi = 0; }
    const float* feat = (const float*)d_in[fi];
    const void*  mask = d_in[mi];

    cudaFuncSetAttribute(maxsim_p1, cudaFuncAttributeMaxDynamicSharedMemorySize,
                         SMEM_BYTES);

    init_kernel<<<(B_ * N_ + 255) / 256, 256>>>();
    zero_tiles_kernel<<<592, 256>>>();
    detect_kernel<<<1, 1024>>>((const unsigned char*)mask);
    norm_compact_kernel<<<(B_ * N_ * 32 + 255) / 256, 256>>>(feat, mask);
    dim3 g(N_ / 128, B_, JSPLIT);
    maxsim_p1<<<g, 256, SMEM_BYTES>>>();
    rescore_kernel<<<(B_ * N_ + 7) / 8, 256>>>();
    finalize_kernel<<<1, 32>>>((float*)d_out);
}